// round 14
// baseline (speedup 1.0000x reference)
#include <cuda_runtime.h>
#include <cuda_fp16.h>
#include <math.h>

#define MAXN 100000
#define F 32
#define CAP 80   // max in-degree bucket (Poisson lambda=16 -> P(deg>=80) ~ 7e-29)
#define AGG_BLOCKS 1036   // ~7 blocks/SM persistent

// Scratch (no allocs allowed). Feature buffers stored as fp16 (uint2 = 4 halves/lane).
__device__ uint2 g_H1[MAXN * 8];     // hs1 = (x@W1)*dinv, half, row = 64B
__device__ uint2 g_H2[MAXN * 8];     // hs2 = (h1@W2)*dinv, half
__device__ int   g_adj[MAXN * CAP];  // fixed-capacity adjacency by dst (16B-aligned rows)
__device__ int   g_cnt[MAXN];        // in-degree / bump pointer
__device__ float g_dinv[MAXN];
__device__ int   g_max[F];           // float-as-int max (relu => >= 0)
__device__ int   g_is64;

// ---------------------------------------------------------------------------
// Init: zero counters/max + PARALLEL dtype detection (128 threads, 1 load each;
// int64 ids < 2^31 -> all odd 32-bit words zero).
__global__ void k_init(const int* __restrict__ ew, int n) {
    __shared__ int s_nz;
    int i = blockIdx.x * blockDim.x + threadIdx.x;
    if (i < n) g_cnt[i] = 0;
    if (i < F) g_max[i] = 0;
    if (blockIdx.x == 0) {
        if (threadIdx.x == 0) s_nz = 0;
        __syncthreads();
        if (threadIdx.x < 128 && ew[2 * threadIdx.x + 1] != 0) s_nz = 1;
        __syncthreads();
        if (threadIdx.x == 0) g_is64 = !s_nz;
    }
}

__device__ __forceinline__ int load_idx(const int* __restrict__ ew, int is64, long long pos) {
    return is64 ? ew[2 * pos] : ew[pos];   // low word of int64
}

// Build bucketed adjacency: adj[dst][pos] = src. One atomic bump per edge.
__global__ void k_fill(const int* __restrict__ ew, int E) {
    int e = blockIdx.x * blockDim.x + threadIdx.x;
    if (e >= E) return;
    int is64 = g_is64;
    int src = load_idx(ew, is64, e);
    int dst = load_idx(ew, is64, (long long)E + e);
    int pos = atomicAdd(&g_cnt[dst], 1);
    if (pos < CAP) g_adj[dst * CAP + pos] = src;
}

// ---------------------------------------------------------------------------
// Layer-1 transform: dinv = rsqrt(deg+1); H1[i,:] = half((x[i,:] @ W1) * dinv).
__global__ void __launch_bounds__(256) k_lin1(const float* __restrict__ x,
                                              const float* __restrict__ W1, int n) {
    __shared__ float sW[8 * F];
    int t = threadIdx.x;
    if (t < 8 * F) sW[t] = W1[t];
    __syncthreads();
    int i = blockIdx.x * (blockDim.x >> 5) + (t >> 5);
    int j = t & 31;
    if (i >= n) return;
    float di = rsqrtf((float)(g_cnt[i] + 1));
    if (j == 0) g_dinv[i] = di;
    float xv = (j < 8) ? x[i * 8 + j] : 0.f;
    float acc = 0.f;
    #pragma unroll
    for (int k = 0; k < 8; k++)
        acc += __shfl_sync(0xffffffffu, xv, k) * sW[k * F + j];
    ((__half*)g_H1)[i * F + j] = __float2half(acc * di);
}

// ---------------------------------------------------------------------------
// Gather core: warp = 4 neighbor-slots x 8 feature-lanes (uint2 = 4 halves).
// Per 16-neighbor chunk each slot loads ONE int4 of contiguous indices, gathers
// 4 rows, tree-sums them in fp16 (6 HADD2), folds to fp32 once per chunk.
// 2-round shfl.xor folds the 4 slots.
__device__ __forceinline__ __half2 u2h(unsigned v) { return *(__half2*)&v; }

__device__ __forceinline__ float4 gather_h(const uint2* __restrict__ A,
                                           const int* __restrict__ adj,
                                           int deg, int i, int slot, int fg) {
    float4 acc = make_float4(0.f, 0.f, 0.f, 0.f);
    if (slot == 0) {   // self loop, counted once
        uint2 v = A[i * 8 + fg];
        float2 lo = __half22float2(u2h(v.x));
        float2 hi = __half22float2(u2h(v.y));
        acc.x = lo.x; acc.y = lo.y; acc.z = hi.x; acc.w = hi.y;
    }
    const uint2 z2 = make_uint2(0u, 0u);
    #pragma unroll 2
    for (int base = 0; base < deg; base += 16) {
        int m = deg - base - 4 * slot;                     // valid rows this slot
        int4 s4 = *(const int4*)(adj + base + 4 * slot);   // 16B-aligned quad
        uint2 b0 = (m > 0) ? A[s4.x * 8 + fg] : z2;
        uint2 b1 = (m > 1) ? A[s4.y * 8 + fg] : z2;
        uint2 b2 = (m > 2) ? A[s4.z * 8 + fg] : z2;
        uint2 b3 = (m > 3) ? A[s4.w * 8 + fg] : z2;
        __half2 u0 = __hadd2(u2h(b0.x), u2h(b1.x));
        __half2 u1 = __hadd2(u2h(b2.x), u2h(b3.x));
        __half2 r0 = __hadd2(u0, u1);
        __half2 v0 = __hadd2(u2h(b0.y), u2h(b1.y));
        __half2 v1 = __hadd2(u2h(b2.y), u2h(b3.y));
        __half2 r1 = __hadd2(v0, v1);
        float2 lo = __half22float2(r0);
        float2 hi = __half22float2(r1);
        acc.x += lo.x; acc.y += lo.y; acc.z += hi.x; acc.w += hi.y;
    }
    #pragma unroll
    for (int off = 8; off <= 16; off <<= 1) {
        acc.x += __shfl_xor_sync(0xffffffffu, acc.x, off);
        acc.y += __shfl_xor_sync(0xffffffffu, acc.y, off);
        acc.z += __shfl_xor_sync(0xffffffffu, acc.z, off);
        acc.w += __shfl_xor_sync(0xffffffffu, acc.w, off);
    }
    return acc;   // full neighbor sum for features [4fg..4fg+3], all lanes
}

// ---------------------------------------------------------------------------
// Persistent fused layer-2: gather + relu(*dinv + b1) + 32x32 W2 transform -> H2.
// Grid-stride over nodes; sW staged ONCE per block.
__global__ void __launch_bounds__(256) k_agg1(const float* __restrict__ b1,
                                              const float* __restrict__ W2, int n) {
    __shared__ float sW[F * F];
    __shared__ float sh[8][F];
    int t = threadIdx.x;
    for (int k = t; k < F * F; k += blockDim.x) sW[k] = W2[k];
    __syncthreads();
    int lane = t & 31, w = t >> 5;
    int slot = lane >> 3, fg = lane & 7;
    int stride = gridDim.x * 8;
    float4 bb = ((const float4*)b1)[fg];
    for (int i = blockIdx.x * 8 + w; i < n; i += stride) {
        int deg = min(g_cnt[i], CAP);
        const int* adj = g_adj + i * CAP;
        float4 acc = gather_h(g_H1, adj, deg, i, slot, fg);
        float di = g_dinv[i];
        float4 h;
        h.x = fmaxf(acc.x * di + bb.x, 0.f);
        h.y = fmaxf(acc.y * di + bb.y, 0.f);
        h.z = fmaxf(acc.z * di + bb.z, 0.f);
        h.w = fmaxf(acc.w * di + bb.w, 0.f);
        if (slot == 0) *(float4*)&sh[w][fg * 4] = h;
        __syncwarp();
        int j = lane;
        float o = 0.f;
        #pragma unroll
        for (int q = 0; q < 8; q++) {
            float4 hq = *(const float4*)&sh[w][q * 4];   // uniform broadcast LDS.128
            o += hq.x * sW[(4 * q + 0) * F + j];
            o += hq.y * sW[(4 * q + 1) * F + j];
            o += hq.z * sW[(4 * q + 2) * F + j];
            o += hq.w * sW[(4 * q + 3) * F + j];
        }
        ((__half*)g_H2)[i * F + j] = __float2half(o * di);
        __syncwarp();   // protect sh[w] before next iteration overwrites
    }
}

// ---------------------------------------------------------------------------
// Persistent fused output layer: gather + relu(*dinv + b2) + max pool.
// Per-warp running max across its nodes; one block reduce + atomicMax at end.
__global__ void __launch_bounds__(256) k_agg2(const float* __restrict__ b2, int n) {
    __shared__ float sm[8][F];
    int t = threadIdx.x;
    int lane = t & 31, w = t >> 5;
    int slot = lane >> 3, fg = lane & 7;
    int stride = gridDim.x * 8;
    float4 bb = ((const float4*)b2)[fg];
    float4 mx = make_float4(0.f, 0.f, 0.f, 0.f);   // relu lower bound
    for (int i = blockIdx.x * 8 + w; i < n; i += stride) {
        int deg = min(g_cnt[i], CAP);
        const int* adj = g_adj + i * CAP;
        float4 acc = gather_h(g_H2, adj, deg, i, slot, fg);
        float di = g_dinv[i];
        mx.x = fmaxf(mx.x, acc.x * di + bb.x);
        mx.y = fmaxf(mx.y, acc.y * di + bb.y);
        mx.z = fmaxf(mx.z, acc.z * di + bb.z);
        mx.w = fmaxf(mx.w, acc.w * di + bb.w);
    }
    if (slot == 0) *(float4*)&sm[w][fg * 4] = mx;   // valid in slot-0 lanes
    __syncthreads();
    if (w == 0) {
        float mm = sm[0][lane];
        #pragma unroll
        for (int k = 1; k < 8; k++) mm = fmaxf(mm, sm[k][lane]);
        atomicMax(&g_max[lane], __float_as_int(mm));
    }
}

// ---------------------------------------------------------------------------
__global__ void k_fc(const float* __restrict__ fcW, const float* __restrict__ fcb,
                     float* __restrict__ out) {
    if (threadIdx.x != 0) return;
    float g[F];
    #pragma unroll
    for (int j = 0; j < F; j++) g[j] = __int_as_float(g_max[j]);
    float lg[5];
    float mx = -1e30f;
    #pragma unroll
    for (int c = 0; c < 5; c++) {
        float a = fcb[c];
        #pragma unroll
        for (int j = 0; j < F; j++) a += g[j] * fcW[j * 5 + c];
        lg[c] = a;
        mx = fmaxf(mx, a);
    }
    float sum = 0.f;
    #pragma unroll
    for (int c = 0; c < 5; c++) sum += expf(lg[c] - mx);
    float l = logf(sum) + mx;
    #pragma unroll
    for (int c = 0; c < 5; c++) out[c] = lg[c] - l;
}

// ---------------------------------------------------------------------------
extern "C" void kernel_launch(void* const* d_in, const int* in_sizes, int n_in,
                              void* d_out, int out_size) {
    const float* x   = (const float*)d_in[0];
    const int*   ew  = (const int*)d_in[1];
    const float* W1  = (const float*)d_in[2];
    const float* b1  = (const float*)d_in[3];
    const float* W2  = (const float*)d_in[4];
    const float* b2  = (const float*)d_in[5];
    const float* fcW = (const float*)d_in[6];
    const float* fcb = (const float*)d_in[7];
    float* out = (float*)d_out;

    int n = in_sizes[0] / 8;      // 100000
    int E = in_sizes[1] / 2;      // 1600000

    k_init<<<(n + 255) / 256, 256>>>(ew, n);
    k_fill<<<(E + 255) / 256, 256>>>(ew, E);
    k_lin1<<<(n + 7) / 8, 256>>>(x, W1, n);
    k_agg1<<<AGG_BLOCKS, 256>>>(b1, W2, n);
    k_agg2<<<AGG_BLOCKS, 256>>>(b2, n);
    k_fc<<<1, 32>>>(fcW, fcb, out);
}

// round 15
// speedup vs baseline: 1.2010x; 1.2010x over previous
#include <cuda_runtime.h>
#include <cuda_fp16.h>
#include <math.h>

#define MAXN 100000
#define F 32
#define CAP 80   // max in-degree bucket (Poisson lambda=16 -> P(deg>=80) ~ 7e-29)

// Scratch (no allocs allowed). Feature buffers stored as fp16 (uint2 = 4 halves/lane).
__device__ uint2 g_H1[MAXN * 8];     // hs1 = (x@W1)*dinv, half, row = 64B
__device__ uint2 g_H2[MAXN * 8];     // hs2 = (h1@W2)*dinv, half
__device__ int   g_adj[MAXN * CAP];  // fixed-capacity adjacency by dst (16B-aligned rows)
__device__ int   g_cnt[MAXN];        // in-degree / bump pointer
__device__ float g_dinv[MAXN];
__device__ int   g_max[F];           // float-as-int max (relu => >= 0)
__device__ int   g_is64;

// ---------------------------------------------------------------------------
// Init: zero counters/max + parallel dtype detection (int64 ids < 2^31 -> all
// odd 32-bit words zero).
__global__ void k_init(const int* __restrict__ ew, int n) {
    __shared__ int s_nz;
    int i = blockIdx.x * blockDim.x + threadIdx.x;
    if (i < n) g_cnt[i] = 0;
    if (i < F) g_max[i] = 0;
    if (blockIdx.x == 0) {
        if (threadIdx.x == 0) s_nz = 0;
        __syncthreads();
        if (threadIdx.x < 128 && ew[2 * threadIdx.x + 1] != 0) s_nz = 1;
        __syncthreads();
        if (threadIdx.x == 0) g_is64 = !s_nz;
    }
}

// Build bucketed adjacency: adj[dst][pos] = src. Two edges per thread,
// vectorized index loads (int4 for i64 pairs, int2 for i32 pairs).
__global__ void k_fill(const int* __restrict__ ew, int E) {
    int t = blockIdx.x * blockDim.x + threadIdx.x;
    int e = 2 * t;
    if (e >= E) return;
    int s0, s1, d0, d1;
    if (g_is64) {
        int4 sv = *(const int4*)(ew + 2 * e);                    // 2 int64 srcs
        int4 dv = *(const int4*)(ew + 2 * (long long)E + 2 * e); // 2 int64 dsts
        s0 = sv.x; s1 = sv.z; d0 = dv.x; d1 = dv.z;
    } else {
        int2 sv = *(const int2*)(ew + e);
        int2 dv = *(const int2*)(ew + E + e);
        s0 = sv.x; s1 = sv.y; d0 = dv.x; d1 = dv.y;
    }
    int p0 = atomicAdd(&g_cnt[d0], 1);
    if (p0 < CAP) g_adj[d0 * CAP + p0] = s0;
    if (e + 1 < E) {
        int p1 = atomicAdd(&g_cnt[d1], 1);
        if (p1 < CAP) g_adj[d1 * CAP + p1] = s1;
    }
}

// ---------------------------------------------------------------------------
// Layer-1 transform: dinv = rsqrt(deg+1); H1[i,:] = half((x[i,:] @ W1) * dinv).
__global__ void __launch_bounds__(256) k_lin1(const float* __restrict__ x,
                                              const float* __restrict__ W1, int n) {
    __shared__ float sW[8 * F];
    int t = threadIdx.x;
    if (t < 8 * F) sW[t] = W1[t];
    __syncthreads();
    int i = blockIdx.x * (blockDim.x >> 5) + (t >> 5);
    int j = t & 31;
    if (i >= n) return;
    float di = rsqrtf((float)(g_cnt[i] + 1));
    if (j == 0) g_dinv[i] = di;
    float xv = (j < 8) ? x[i * 8 + j] : 0.f;
    float acc = 0.f;
    #pragma unroll
    for (int k = 0; k < 8; k++)
        acc += __shfl_sync(0xffffffffu, xv, k) * sW[k * F + j];
    ((__half*)g_H1)[i * F + j] = __float2half(acc * di);
}

// ---------------------------------------------------------------------------
// Dual-node gather: warp = 4 slots x 8 feature-lanes, TWO nodes interleaved so
// both idx->value LDG chains overlap (2 int4 idx loads + 8 predicated value
// loads in flight). fp16 pair-tree per chunk, fp32 accumulate, shfl.xor fold.
__device__ __forceinline__ __half2 u2h(unsigned v) { return *(__half2*)&v; }

__device__ __forceinline__ void self_h(float4& acc, const uint2* A, int i, int fg) {
    uint2 v = A[i * 8 + fg];
    float2 lo = __half22float2(u2h(v.x));
    float2 hi = __half22float2(u2h(v.y));
    acc.x = lo.x; acc.y = lo.y; acc.z = hi.x; acc.w = hi.y;
}

__device__ __forceinline__ void chunk_h(float4& acc, const uint2* __restrict__ A,
                                        int4 s4, int m, int fg, uint2 z2) {
    uint2 b0 = (m > 0) ? A[s4.x * 8 + fg] : z2;
    uint2 b1 = (m > 1) ? A[s4.y * 8 + fg] : z2;
    uint2 b2 = (m > 2) ? A[s4.z * 8 + fg] : z2;
    uint2 b3 = (m > 3) ? A[s4.w * 8 + fg] : z2;
    __half2 u0 = __hadd2(u2h(b0.x), u2h(b1.x));
    __half2 u1 = __hadd2(u2h(b2.x), u2h(b3.x));
    __half2 r0 = __hadd2(u0, u1);
    __half2 v0 = __hadd2(u2h(b0.y), u2h(b1.y));
    __half2 v1 = __hadd2(u2h(b2.y), u2h(b3.y));
    __half2 r1 = __hadd2(v0, v1);
    float2 lo = __half22float2(r0);
    float2 hi = __half22float2(r1);
    acc.x += lo.x; acc.y += lo.y; acc.z += hi.x; acc.w += hi.y;
}

__device__ __forceinline__ void gather2_h(float4& a0, float4& a1,
                                          const uint2* __restrict__ A,
                                          int i0, int i1, int deg0, int deg1,
                                          int slot, int fg) {
    a0 = make_float4(0.f, 0.f, 0.f, 0.f);
    a1 = make_float4(0.f, 0.f, 0.f, 0.f);
    if (slot == 0) { self_h(a0, A, i0, fg); self_h(a1, A, i1, fg); }
    const uint2 z2 = make_uint2(0u, 0u);
    const int* adj0 = g_adj + i0 * CAP;
    const int* adj1 = g_adj + i1 * CAP;
    int dmax = max(deg0, deg1);
    #pragma unroll 1
    for (int base = 0; base < dmax; base += 16) {
        int off = base + 4 * slot;
        int m0 = deg0 - off, m1 = deg1 - off;
        // quads always within the CAP=80 row; values predicated by m.
        int4 s0 = *(const int4*)(adj0 + off);
        int4 s1 = *(const int4*)(adj1 + off);
        chunk_h(a0, A, s0, m0, fg, z2);
        chunk_h(a1, A, s1, m1, fg, z2);
    }
    #pragma unroll
    for (int off = 8; off <= 16; off <<= 1) {
        a0.x += __shfl_xor_sync(0xffffffffu, a0.x, off);
        a0.y += __shfl_xor_sync(0xffffffffu, a0.y, off);
        a0.z += __shfl_xor_sync(0xffffffffu, a0.z, off);
        a0.w += __shfl_xor_sync(0xffffffffu, a0.w, off);
        a1.x += __shfl_xor_sync(0xffffffffu, a1.x, off);
        a1.y += __shfl_xor_sync(0xffffffffu, a1.y, off);
        a1.z += __shfl_xor_sync(0xffffffffu, a1.z, off);
        a1.w += __shfl_xor_sync(0xffffffffu, a1.w, off);
    }
}

// ---------------------------------------------------------------------------
// Fused layer-2: dual gather + relu(*dinv + b1) + 32x32 W2 transform -> H2.
// Block = 8 warps = 16 nodes. n = 100000 is divisible by 16 via clamp trick.
__global__ void __launch_bounds__(256) k_agg1(const float* __restrict__ b1,
                                              const float* __restrict__ W2, int n) {
    __shared__ float sW[F * F];
    __shared__ float sh[8][2][F];
    int t = threadIdx.x;
    for (int k = t; k < F * F; k += blockDim.x) sW[k] = W2[k];
    __syncthreads();
    int lane = t & 31, w = t >> 5;
    int slot = lane >> 3, fg = lane & 7;
    int i0 = blockIdx.x * 16 + 2 * w;
    if (i0 >= n) return;
    int i1 = min(i0 + 1, n - 1);           // clamp: duplicate compute is harmless
    int deg0 = min(g_cnt[i0], CAP);
    int deg1 = min(g_cnt[i1], CAP);
    float di0 = g_dinv[i0], di1 = g_dinv[i1];
    float4 a0, a1;
    gather2_h(a0, a1, g_H1, i0, i1, deg0, deg1, slot, fg);
    float4 bb = ((const float4*)b1)[fg];
    if (slot == 0) {
        float4 h0, h1;
        h0.x = fmaxf(a0.x * di0 + bb.x, 0.f);
        h0.y = fmaxf(a0.y * di0 + bb.y, 0.f);
        h0.z = fmaxf(a0.z * di0 + bb.z, 0.f);
        h0.w = fmaxf(a0.w * di0 + bb.w, 0.f);
        h1.x = fmaxf(a1.x * di1 + bb.x, 0.f);
        h1.y = fmaxf(a1.y * di1 + bb.y, 0.f);
        h1.z = fmaxf(a1.z * di1 + bb.z, 0.f);
        h1.w = fmaxf(a1.w * di1 + bb.w, 0.f);
        *(float4*)&sh[w][0][fg * 4] = h0;
        *(float4*)&sh[w][1][fg * 4] = h1;
    }
    __syncwarp();
    int j = lane;
    float o0 = 0.f, o1 = 0.f;
    #pragma unroll
    for (int q = 0; q < 8; q++) {
        float4 hq0 = *(const float4*)&sh[w][0][q * 4];   // broadcast LDS.128
        float4 hq1 = *(const float4*)&sh[w][1][q * 4];
        o0 += hq0.x * sW[(4 * q + 0) * F + j];
        o0 += hq0.y * sW[(4 * q + 1) * F + j];
        o0 += hq0.z * sW[(4 * q + 2) * F + j];
        o0 += hq0.w * sW[(4 * q + 3) * F + j];
        o1 += hq1.x * sW[(4 * q + 0) * F + j];
        o1 += hq1.y * sW[(4 * q + 1) * F + j];
        o1 += hq1.z * sW[(4 * q + 2) * F + j];
        o1 += hq1.w * sW[(4 * q + 3) * F + j];
    }
    ((__half*)g_H2)[i0 * F + j] = __float2half(o0 * di0);
    ((__half*)g_H2)[i1 * F + j] = __float2half(o1 * di1);
}

// ---------------------------------------------------------------------------
// Fused output layer: dual gather + relu(*dinv + b2) + block max pool.
__global__ void __launch_bounds__(256) k_agg2(const float* __restrict__ b2, int n) {
    __shared__ float sm[8][F];
    int t = threadIdx.x;
    int lane = t & 31, w = t >> 5;
    int slot = lane >> 3, fg = lane & 7;
    int i0 = blockIdx.x * 16 + 2 * w;
    float4 mx = make_float4(0.f, 0.f, 0.f, 0.f);   // relu lower bound
    if (i0 < n) {
        int i1 = min(i0 + 1, n - 1);
        int deg0 = min(g_cnt[i0], CAP);
        int deg1 = min(g_cnt[i1], CAP);
        float di0 = g_dinv[i0], di1 = g_dinv[i1];
        float4 a0, a1;
        gather2_h(a0, a1, g_H2, i0, i1, deg0, deg1, slot, fg);
        float4 bb = ((const float4*)b2)[fg];
        mx.x = fmaxf(a0.x * di0 + bb.x, a1.x * di1 + bb.x);
        mx.y = fmaxf(a0.y * di0 + bb.y, a1.y * di1 + bb.y);
        mx.z = fmaxf(a0.z * di0 + bb.z, a1.z * di1 + bb.z);
        mx.w = fmaxf(a0.w * di0 + bb.w, a1.w * di1 + bb.w);
        mx.x = fmaxf(mx.x, 0.f); mx.y = fmaxf(mx.y, 0.f);
        mx.z = fmaxf(mx.z, 0.f); mx.w = fmaxf(mx.w, 0.f);
    }
    if (slot == 0) *(float4*)&sm[w][fg * 4] = mx;   // slot-0 lanes hold the full sum
    __syncthreads();
    if (w == 0) {
        float mm = sm[0][lane];
        #pragma unroll
        for (int k = 1; k < 8; k++) mm = fmaxf(mm, sm[k][lane]);
        atomicMax(&g_max[lane], __float_as_int(mm));
    }
}

// ---------------------------------------------------------------------------
__global__ void k_fc(const float* __restrict__ fcW, const float* __restrict__ fcb,
                     float* __restrict__ out) {
    if (threadIdx.x != 0) return;
    float g[F];
    #pragma unroll
    for (int j = 0; j < F; j++) g[j] = __int_as_float(g_max[j]);
    float lg[5];
    float mx = -1e30f;
    #pragma unroll
    for (int c = 0; c < 5; c++) {
        float a = fcb[c];
        #pragma unroll
        for (int j = 0; j < F; j++) a += g[j] * fcW[j * 5 + c];
        lg[c] = a;
        mx = fmaxf(mx, a);
    }
    float sum = 0.f;
    #pragma unroll
    for (int c = 0; c < 5; c++) sum += expf(lg[c] - mx);
    float l = logf(sum) + mx;
    #pragma unroll
    for (int c = 0; c < 5; c++) out[c] = lg[c] - l;
}

// ---------------------------------------------------------------------------
extern "C" void kernel_launch(void* const* d_in, const int* in_sizes, int n_in,
                              void* d_out, int out_size) {
    const float* x   = (const float*)d_in[0];
    const int*   ew  = (const int*)d_in[1];
    const float* W1  = (const float*)d_in[2];
    const float* b1  = (const float*)d_in[3];
    const float* W2  = (const float*)d_in[4];
    const float* b2  = (const float*)d_in[5];
    const float* fcW = (const float*)d_in[6];
    const float* fcb = (const float*)d_in[7];
    float* out = (float*)d_out;

    int n = in_sizes[0] / 8;      // 100000
    int E = in_sizes[1] / 2;      // 1600000

    k_init<<<(n + 255) / 256, 256>>>(ew, n);
    k_fill<<<(E / 2 + 255) / 256, 256>>>(ew, E);
    k_lin1<<<(n + 7) / 8, 256>>>(x, W1, n);
    int ab = (n + 15) / 16;
    k_agg1<<<ab, 256>>>(b1, W2, n);
    k_agg2<<<ab, 256>>>(b2, n);
    k_fc<<<1, 32>>>(fcW, fcb, out);
}